// round 1
// baseline (speedup 1.0000x reference)
#include <cuda_runtime.h>

// 32 images * 8 * 8 blocks = 2048 block partials
#define NUM_BLOCKS_TOTAL 2048
__device__ float g_partials[NUM_BLOCKS_TOTAL];

// One CTA per 128x128 tile. Computes |sum(fake - real)| over the tile.
__global__ __launch_bounds__(256) void tile_absdiff_kernel(
    const float* __restrict__ fake, const float* __restrict__ real)
{
    const int blk = blockIdx.x;            // 0..2047
    const int b   = blk >> 6;              // image index (64 tiles per image)
    const int rem = blk & 63;
    const int by  = rem >> 3;              // tile row 0..7
    const int bx  = rem & 7;               // tile col 0..7

    // base element offset of tile (C=1)
    const long base = (long)b * (1024 * 1024) + (long)by * 128 * 1024 + (long)bx * 128;

    const float4* f4 = (const float4*)(fake + base);
    const float4* r4 = (const float4*)(real + base);
    // tile: 128 rows x 32 float4/row; row stride in float4 = 1024/4 = 256

    float acc = 0.0f;
    // 4096 float4 per tile, 256 threads -> 16 iterations, unrolled for MLP
    #pragma unroll
    for (int it = 0; it < 16; ++it) {
        int i   = threadIdx.x + it * 256;  // 0..4095
        int row = i >> 5;                  // /32
        int c4  = i & 31;
        float4 fv = f4[row * 256 + c4];
        float4 rv = r4[row * 256 + c4];
        acc += (fv.x - rv.x) + (fv.y - rv.y) + (fv.z - rv.z) + (fv.w - rv.w);
    }

    // warp reduce
    #pragma unroll
    for (int off = 16; off > 0; off >>= 1)
        acc += __shfl_xor_sync(0xFFFFFFFFu, acc, off);

    __shared__ float warp_sums[8];
    int wid = threadIdx.x >> 5;
    int lid = threadIdx.x & 31;
    if (lid == 0) warp_sums[wid] = acc;
    __syncthreads();

    if (wid == 0) {
        float v = (lid < 8) ? warp_sums[lid] : 0.0f;
        #pragma unroll
        for (int off = 4; off > 0; off >>= 1)
            v += __shfl_xor_sync(0xFFFFFFFFu, v, off);
        if (lid == 0) g_partials[blk] = fabsf(v);
    }
}

// Single CTA: reduce 2048 partials -> scalar
__global__ __launch_bounds__(256) void final_reduce_kernel(float* __restrict__ out)
{
    float acc = 0.0f;
    #pragma unroll
    for (int it = 0; it < 8; ++it)
        acc += g_partials[threadIdx.x + it * 256];

    #pragma unroll
    for (int off = 16; off > 0; off >>= 1)
        acc += __shfl_xor_sync(0xFFFFFFFFu, acc, off);

    __shared__ float warp_sums[8];
    int wid = threadIdx.x >> 5;
    int lid = threadIdx.x & 31;
    if (lid == 0) warp_sums[wid] = acc;
    __syncthreads();

    if (wid == 0) {
        float v = (lid < 8) ? warp_sums[lid] : 0.0f;
        #pragma unroll
        for (int off = 4; off > 0; off >>= 1)
            v += __shfl_xor_sync(0xFFFFFFFFu, v, off);
        if (lid == 0)
            out[0] = v * (1.0f / (16384.0f * 32.0f));
    }
}

extern "C" void kernel_launch(void* const* d_in, const int* in_sizes, int n_in,
                              void* d_out, int out_size)
{
    const float* fake = (const float*)d_in[0];
    const float* real = (const float*)d_in[1];
    float* out = (float*)d_out;

    tile_absdiff_kernel<<<NUM_BLOCKS_TOTAL, 256>>>(fake, real);
    final_reduce_kernel<<<1, 256>>>(out);
}